// round 8
// baseline (speedup 1.0000x reference)
#include <cuda_runtime.h>

// Problem constants (fixed by setup_inputs)
#define BB 16
#define HH 2048
#define WW 2048
#define SS 5000
#define NST (BB * SS)          // 80000 stations

#define THREADS 256
#define NBLK 152                           // exactly one wave on 152 SMs
#define TOTTH (NBLK * THREADS)             // 38912 threads
#define LEFTOVER (NST - 2 * TOTTH)         // 2176 stations get a 3rd pass

#define INV_NST (1.0f / (float)NST)

// Select element r (0..3) from the 4-float window {a.x, a.y, b.x, b.y}.
__device__ __forceinline__ float sel4(float2 a, float2 b, int r)
{
    const float lo = (r & 1) ? a.y : a.x;
    const float hi = (r & 1) ? b.y : b.x;
    return (r & 2) ? hi : lo;
}

// Full per-station loss: 3x3 clipped-window mean vs runoff, squared error.
__device__ __forceinline__ float station_loss(const float* __restrict__ pred,
                                              const int*   __restrict__ pos,
                                              const float* __restrict__ runoff,
                                              int sid)
{
    const int b = sid / SS;
    const int2 pxy = __ldg((const int2*)pos + sid);  // .x = px (width), .y = py (height)
    const int x = pxy.x;
    const int y = pxy.y;
    const float* __restrict__ p = pred + (long long)b * (HH * WW);

    // Column window: two float2 loads starting at even xa cover
    // {clamp(x-1), x, clamp(x+1)}.
    int xa = max(x - 1, 0);
    xa = min(xa, WW - 4);
    xa &= ~1;

    const int ym1 = max(y - 1, 0);
    const int yp1 = min(y + 1, HH - 1);

    const float* r0 = p + ym1 * WW + xa;
    const float* r1 = p + y   * WW + xa;
    const float* r2 = p + yp1 * WW + xa;

    const float2 a0 = __ldg((const float2*)(r0));
    const float2 b0 = __ldg((const float2*)(r0 + 2));
    const float2 a1 = __ldg((const float2*)(r1));
    const float2 b1 = __ldg((const float2*)(r1 + 2));
    const float2 a2 = __ldg((const float2*)(r2));
    const float2 b2 = __ldg((const float2*)(r2 + 2));
    const float  ro = __ldg(runoff + sid);

    const int xm1 = max(x - 1, 0);
    const int xp1 = min(x + 1, WW - 1);
    const int rA = xm1 - xa;
    const int rB = x   - xa;
    const int rC = xp1 - xa;

    // Separable validity: mask = colflag x rowflag (rank-1).
    const float f0 = (x - 1 >= 0) ? 1.0f : 0.0f;
    const float f2 = (x + 1 < WW) ? 1.0f : 0.0f;
    const float g0 = (y - 1 >= 0) ? 1.0f : 0.0f;
    const float g2 = (y + 1 < HH) ? 1.0f : 0.0f;
    const float cnt = (1.0f + f0 + f2) * (1.0f + g0 + g2);

    const float s0 = f0 * sel4(a0, b0, rA) + sel4(a0, b0, rB) + f2 * sel4(a0, b0, rC);
    const float s1 = f0 * sel4(a1, b1, rA) + sel4(a1, b1, rB) + f2 * sel4(a1, b1, rC);
    const float s2 = f0 * sel4(a2, b2, rA) + sel4(a2, b2, rB) + f2 * sel4(a2, b2, rC);

    const float sum  = g0 * s0 + s1 + g2 * s2;
    const float avg  = sum / cnt;
    const float diff = avg - ro;
    return diff * diff;
}

__global__ __launch_bounds__(THREADS)
void station_loss_kernel(const float* __restrict__ pred,
                         const int*   __restrict__ pos,
                         const float* __restrict__ runoff,
                         float*       __restrict__ out)
{
    const int tid = blockIdx.x * blockDim.x + threadIdx.x;

    // 2 stations per thread (independent load chains -> MLP ~14),
    // plus a 3rd for the first LEFTOVER threads. Single wave: 152 blocks.
    float acc = station_loss(pred, pos, runoff, tid)
              + station_loss(pred, pos, runoff, tid + TOTTH);
    if (tid < LEFTOVER)
        acc += station_loss(pred, pos, runoff, tid + 2 * TOTTH);

    // Deterministic block reduction: warp shuffle then shared-mem tree.
    __shared__ float smem[THREADS / 32];
    float v = acc;
    #pragma unroll
    for (int off = 16; off > 0; off >>= 1)
        v += __shfl_down_sync(0xFFFFFFFFu, v, off);
    const int lane = threadIdx.x & 31;
    const int warp = threadIdx.x >> 5;
    if (lane == 0) smem[warp] = v;
    __syncthreads();
    if (warp == 0) {
        v = (lane < THREADS / 32) ? smem[lane] : 0.0f;
        #pragma unroll
        for (int off = 16; off > 0; off >>= 1)
            v += __shfl_down_sync(0xFFFFFFFFu, v, off);
        // Fire-and-forget global reduction: one RED.ADD.F32 per block.
        // d_out is zeroed by the leading memset node each replay.
        if (lane == 0) atomicAdd(out, v * INV_NST);
    }
}

extern "C" void kernel_launch(void* const* d_in, const int* in_sizes, int n_in,
                              void* d_out, int out_size)
{
    const float* pred   = (const float*)d_in[0];  // (16,1,2048,2048) f32
    const int*   pos    = (const int*)  d_in[1];  // (16,5000,2) i32
    const float* runoff = (const float*)d_in[2];  // (16,5000) f32
    float* out = (float*)d_out;

    // Zero the 4-byte accumulator (graph-capturable async memset node).
    cudaMemsetAsync(out, 0, sizeof(float), 0);

    station_loss_kernel<<<NBLK, THREADS>>>(pred, pos, runoff, out);
}

// round 9
// speedup vs baseline: 1.1969x; 1.1969x over previous
#include <cuda_runtime.h>

// Problem constants (fixed by setup_inputs)
#define BB 16
#define HH 2048
#define WW 2048
#define SS 5000
#define NST (BB * SS)          // 80000 stations

#define THREADS 256
#define NBLK 157                           // ceil(80000 / (2*256)) -> one wave
#define TOTTH (NBLK * THREADS)             // 40192 threads

#define INV_NST (1.0f / (float)NST)

// Volatile PTX loads: volatile asms keep source order, so all loads issued
// through these helpers are batched back-to-back (max MLP) and cannot be
// sunk to their consumption points by ptxas.
__device__ __forceinline__ float2 ldg_f2(const float* p)
{
    float2 v;
    asm volatile("ld.global.nc.v2.f32 {%0,%1}, [%2];"
                 : "=f"(v.x), "=f"(v.y) : "l"(p));
    return v;
}
__device__ __forceinline__ int2 ldg_i2(const int* p)
{
    int2 v;
    asm volatile("ld.global.nc.v2.s32 {%0,%1}, [%2];"
                 : "=r"(v.x), "=r"(v.y) : "l"(p));
    return v;
}
__device__ __forceinline__ float ldg_f1(const float* p)
{
    float v;
    asm volatile("ld.global.nc.f32 %0, [%1];" : "=f"(v) : "l"(p));
    return v;
}

// Select element r (0..3) from the 4-float window {a.x, a.y, b.x, b.y}.
__device__ __forceinline__ float sel4(float2 a, float2 b, int r)
{
    const float lo = (r & 1) ? a.y : a.x;
    const float hi = (r & 1) ? b.y : b.x;
    return (r & 2) ? hi : lo;
}

struct StAddr {
    const float* r0;
    const float* r1;
    const float* r2;
    int rA, rB, rC;
    float f0, f2, g0, g2;
};

__device__ __forceinline__ StAddr make_addr(const float* __restrict__ pred,
                                            int b, int x, int y)
{
    StAddr s;
    const float* p = pred + (long long)b * (HH * WW);

    int xa = max(x - 1, 0);
    xa = min(xa, WW - 4);
    xa &= ~1;

    const int ym1 = max(y - 1, 0);
    const int yp1 = min(y + 1, HH - 1);

    s.r0 = p + ym1 * WW + xa;
    s.r1 = p + y   * WW + xa;
    s.r2 = p + yp1 * WW + xa;

    const int xm1 = max(x - 1, 0);
    const int xp1 = min(x + 1, WW - 1);
    s.rA = xm1 - xa;
    s.rB = x   - xa;
    s.rC = xp1 - xa;

    s.f0 = (x - 1 >= 0) ? 1.0f : 0.0f;
    s.f2 = (x + 1 < WW) ? 1.0f : 0.0f;
    s.g0 = (y - 1 >= 0) ? 1.0f : 0.0f;
    s.g2 = (y + 1 < HH) ? 1.0f : 0.0f;
    return s;
}

__device__ __forceinline__ float window_loss(const StAddr& s,
                                             float2 a0, float2 b0,
                                             float2 a1, float2 b1,
                                             float2 a2, float2 b2,
                                             float ro)
{
    const float cnt = (1.0f + s.f0 + s.f2) * (1.0f + s.g0 + s.g2);
    const float s0 = s.f0 * sel4(a0, b0, s.rA) + sel4(a0, b0, s.rB) + s.f2 * sel4(a0, b0, s.rC);
    const float s1 = s.f0 * sel4(a1, b1, s.rA) + sel4(a1, b1, s.rB) + s.f2 * sel4(a1, b1, s.rC);
    const float s2 = s.f0 * sel4(a2, b2, s.rA) + sel4(a2, b2, s.rB) + s.f2 * sel4(a2, b2, s.rC);
    const float sum  = s.g0 * s0 + s1 + s.g2 * s2;
    const float avg  = sum / cnt;
    const float diff = avg - ro;
    return diff * diff;
}

__global__ __launch_bounds__(THREADS)
void station_loss_kernel(const float* __restrict__ pred,
                         const int*   __restrict__ pos,
                         const float* __restrict__ runoff,
                         float*       __restrict__ out)
{
    const int tid = blockIdx.x * blockDim.x + threadIdx.x;

    // Station 0 always valid (TOTTH=40192 <= NST); station 1 predicated.
    const int  sid0 = tid;
    const bool has1 = (tid + TOTTH) < NST;
    const int  sid1 = has1 ? (tid + TOTTH) : tid;   // clamp: safe duplicate
    const float m1  = has1 ? 1.0f : 0.0f;

    // Phase 1: both position loads (batched).
    const int2 p0 = ldg_i2(pos + 2 * sid0);
    const int2 p1 = ldg_i2(pos + 2 * sid1);

    // Phase 2: address generation for both stations.
    const StAddr A = make_addr(pred, sid0 / SS, p0.x, p0.y);
    const StAddr B = make_addr(pred, sid1 / SS, p1.x, p1.y);

    // Phase 3: ALL 12 window loads + 2 runoff loads, issued back-to-back.
    const float2 Aa0 = ldg_f2(A.r0);
    const float2 Ab0 = ldg_f2(A.r0 + 2);
    const float2 Aa1 = ldg_f2(A.r1);
    const float2 Ab1 = ldg_f2(A.r1 + 2);
    const float2 Aa2 = ldg_f2(A.r2);
    const float2 Ab2 = ldg_f2(A.r2 + 2);
    const float2 Ba0 = ldg_f2(B.r0);
    const float2 Bb0 = ldg_f2(B.r0 + 2);
    const float2 Ba1 = ldg_f2(B.r1);
    const float2 Bb1 = ldg_f2(B.r1 + 2);
    const float2 Ba2 = ldg_f2(B.r2);
    const float2 Bb2 = ldg_f2(B.r2 + 2);
    const float  ro0 = ldg_f1(runoff + sid0);
    const float  ro1 = ldg_f1(runoff + sid1);

    // Phase 4: arithmetic.
    const float acc = window_loss(A, Aa0, Ab0, Aa1, Ab1, Aa2, Ab2, ro0)
              + m1 * window_loss(B, Ba0, Bb0, Ba1, Bb1, Ba2, Bb2, ro1);

    // Deterministic block reduction: warp shuffle then shared-mem tree.
    __shared__ float smem[THREADS / 32];
    float v = acc;
    #pragma unroll
    for (int off = 16; off > 0; off >>= 1)
        v += __shfl_down_sync(0xFFFFFFFFu, v, off);
    const int lane = threadIdx.x & 31;
    const int warp = threadIdx.x >> 5;
    if (lane == 0) smem[warp] = v;
    __syncthreads();
    if (warp == 0) {
        v = (lane < THREADS / 32) ? smem[lane] : 0.0f;
        #pragma unroll
        for (int off = 16; off > 0; off >>= 1)
            v += __shfl_down_sync(0xFFFFFFFFu, v, off);
        // Fire-and-forget global reduction: one RED.ADD.F32 per block.
        if (lane == 0) atomicAdd(out, v * INV_NST);
    }
}

extern "C" void kernel_launch(void* const* d_in, const int* in_sizes, int n_in,
                              void* d_out, int out_size)
{
    const float* pred   = (const float*)d_in[0];  // (16,1,2048,2048) f32
    const int*   pos    = (const int*)  d_in[1];  // (16,5000,2) i32
    const float* runoff = (const float*)d_in[2];  // (16,5000) f32
    float* out = (float*)d_out;

    // Zero the 4-byte accumulator (graph-capturable async memset node).
    cudaMemsetAsync(out, 0, sizeof(float), 0);

    station_loss_kernel<<<NBLK, THREADS>>>(pred, pos, runoff, out);
}